// round 3
// baseline (speedup 1.0000x reference)
#include <cuda_runtime.h>
#include <cstdint>

#define NN 6400
#define CC 64
#define HH 80

using u64 = unsigned long long;

__device__ float d_S1[HH];

// ---------------------------------------------------------------------------
// packed f32x2 helpers (Blackwell-only; ptxas won't auto-fuse from C++)
// ---------------------------------------------------------------------------
__device__ __forceinline__ u64 pk2(float lo, float hi) {
    u64 r; asm("mov.b64 %0, {%1, %2};" : "=l"(r) : "f"(lo), "f"(hi)); return r;
}
__device__ __forceinline__ void fma2(u64& d, u64 a, u64 b) {
    asm("fma.rn.f32x2 %0, %1, %2, %0;" : "+l"(d) : "l"(a), "l"(b));
}
__device__ __forceinline__ float2 up2(u64 v) {
    float2 f; asm("mov.b64 {%0, %1}, %2;" : "=f"(f.x), "=f"(f.y) : "l"(v)); return f;
}

// ---------------------------------------------------------------------------
// k0: S1[r] = sum_{r'} exp(-(r-r')^2/2)   (80 entries)
// ---------------------------------------------------------------------------
__global__ void k0_tables() {
    __shared__ float sE[HH];
    int t = threadIdx.x;
    if (t < HH) sE[t] = __expf(-0.5f * (float)(t * t));
    __syncthreads();
    if (t < HH) {
        float s = 0.0f;
        #pragma unroll 8
        for (int r = 0; r < HH; r++) {
            int d = t - r; d = d < 0 ? -d : d;
            s += sE[d];
        }
        d_S1[t] = s;
    }
}

// ---------------------------------------------------------------------------
// k1: fused  [ S = X @ X^T  (raw logits into As region) ]  +  [ analytic Ad ].
// CTA tile 64 rows x 128 cols, 256 threads, 4x8 micro-tile, f32x2 packed FFMA.
// Each thread also writes its own 4x8 footprint of Ad (pure MUFU+STG, overlaps
// the FMA-bound mainloop; DRAM is otherwise idle during the GEMM).
// ---------------------------------------------------------------------------
__global__ __launch_bounds__(256, 2) void k1_gemm(const float* __restrict__ X,
                                                  float* __restrict__ As,
                                                  float* __restrict__ Ad) {
    __shared__ float sA[CC * 64];     // k-major: sA[k*64 + r]
    __shared__ float sB[CC * 128];    // k-major: sB[k*128 + c]

    const int tid = threadIdx.x;
    const int c0 = blockIdx.x * 128;
    const int r0 = blockIdx.y * 64;

    // ---- load A tile (64 rows x 64 k) transposed ----
    {
        int ar = tid & 63;
        int kq = tid >> 6;                 // 0..3 -> k block of 16
        const float4* src =
            reinterpret_cast<const float4*>(X + (size_t)(r0 + ar) * CC) + kq * 4;
        #pragma unroll
        for (int q = 0; q < 4; q++) {
            float4 v = src[q];
            int k = kq * 16 + q * 4;
            sA[(k + 0) * 64 + ar] = v.x;
            sA[(k + 1) * 64 + ar] = v.y;
            sA[(k + 2) * 64 + ar] = v.z;
            sA[(k + 3) * 64 + ar] = v.w;
        }
    }
    // ---- load B tile (128 cols x 64 k) transposed ----
    {
        int bc = tid & 127;
        int h  = tid >> 7;                 // 0..1 -> k half of 32
        const float4* src =
            reinterpret_cast<const float4*>(X + (size_t)(c0 + bc) * CC + h * 32);
        #pragma unroll
        for (int q = 0; q < 8; q++) {
            float4 v = src[q];
            int k = h * 32 + q * 4;
            sB[(k + 0) * 128 + bc] = v.x;
            sB[(k + 1) * 128 + bc] = v.y;
            sB[(k + 2) * 128 + bc] = v.z;
            sB[(k + 3) * 128 + bc] = v.w;
        }
    }
    __syncthreads();

    const int wid = tid >> 5, lane = tid & 31;
    const int warp_r = wid & 3;            // 4 row-groups of 16
    const int warp_c = wid >> 2;           // 2 col-groups of 64
    const int lr = lane >> 3;              // 0..3 -> 4-row subgroup
    const int lc = lane & 7;               // 0..7 -> 8-col subgroup
    const int tr = warp_r * 16 + lr * 4;   // first of this thread's 4 rows
    const int tc = warp_c * 64 + lc * 8;   // first of this thread's 8 cols

    // ================= fused Ad block (same 4x8 footprint) =================
    {
        const int gj0 = c0 + tc;
        int rj[8], cj[8];
        {
            int rj0 = gj0 / HH;
            int cj0 = gj0 - rj0 * HH;
            #pragma unroll
            for (int c = 0; c < 8; c++) {
                int cc2 = cj0 + c, rr = rj0;
                if (cc2 >= HH) { cc2 -= HH; rr += 1; }
                rj[c] = rr; cj[c] = cc2;
            }
        }
        #pragma unroll
        for (int r = 0; r < 4; r++) {
            int i  = r0 + tr + r;
            int ri = i / HH, ci = i - ri * HH;
            float inv = 1.0f / (__ldg(&d_S1[ri]) * __ldg(&d_S1[ci]) - 1.0f);
            float vo[8];
            #pragma unroll
            for (int c = 0; c < 8; c++) {
                int dr = ri - rj[c];
                int dc = ci - cj[c];
                float d2 = (float)(dr * dr + dc * dc);
                float v  = __expf(-0.5f * d2) * inv;
                vo[c] = (i == gj0 + c) ? 0.0f : v;
            }
            float4* o = reinterpret_cast<float4*>(Ad + (size_t)i * NN + gj0);
            o[0] = make_float4(vo[0], vo[1], vo[2], vo[3]);
            o[1] = make_float4(vo[4], vo[5], vo[6], vo[7]);
        }
    }

    // ======================= f32x2 GEMM mainloop ===========================
    u64 acc[4][4];
    #pragma unroll
    for (int i = 0; i < 4; i++)
        #pragma unroll
        for (int j = 0; j < 4; j++)
            acc[i][j] = 0ull;

    #pragma unroll 8
    for (int k = 0; k < CC; k++) {
        float4 a  = *reinterpret_cast<const float4*>(&sA[k * 64 + tr]);
        float4 b0 = *reinterpret_cast<const float4*>(&sB[k * 128 + tc]);
        float4 b1 = *reinterpret_cast<const float4*>(&sB[k * 128 + tc + 4]);

        u64 bb0 = pk2(b0.x, b0.y);
        u64 bb1 = pk2(b0.z, b0.w);
        u64 bb2 = pk2(b1.x, b1.y);
        u64 bb3 = pk2(b1.z, b1.w);

        u64 a0 = pk2(a.x, a.x);
        u64 a1 = pk2(a.y, a.y);
        u64 a2 = pk2(a.z, a.z);
        u64 a3 = pk2(a.w, a.w);

        fma2(acc[0][0], a0, bb0); fma2(acc[0][1], a0, bb1);
        fma2(acc[0][2], a0, bb2); fma2(acc[0][3], a0, bb3);
        fma2(acc[1][0], a1, bb0); fma2(acc[1][1], a1, bb1);
        fma2(acc[1][2], a1, bb2); fma2(acc[1][3], a1, bb3);
        fma2(acc[2][0], a2, bb0); fma2(acc[2][1], a2, bb1);
        fma2(acc[2][2], a2, bb2); fma2(acc[2][3], a2, bb3);
        fma2(acc[3][0], a3, bb0); fma2(acc[3][1], a3, bb1);
        fma2(acc[3][2], a3, bb2); fma2(acc[3][3], a3, bb3);
    }

    // ============================ epilogue =================================
    float* out = As + (size_t)(r0 + tr) * NN + c0 + tc;
    #pragma unroll
    for (int r = 0; r < 4; r++) {
        float2 p0 = up2(acc[r][0]);
        float2 p1 = up2(acc[r][1]);
        float2 p2 = up2(acc[r][2]);
        float2 p3 = up2(acc[r][3]);
        float4* o = reinterpret_cast<float4*>(out + (size_t)r * NN);
        o[0] = make_float4(p0.x, p0.y, p1.x, p1.y);
        o[1] = make_float4(p2.x, p2.y, p3.x, p3.y);
    }
}

// ---------------------------------------------------------------------------
// k2: per-row softmax finalize (in place). One row per CTA, 512 threads.
// mean(softmax_row) == 1/N exactly, so threshold = 1/N.
// ---------------------------------------------------------------------------
__global__ __launch_bounds__(512) void k2_softmax(float* __restrict__ S) {
    __shared__ float4 sbuf[NN / 4];   // 25.6 KB row cache
    __shared__ float  sred[16];

    const int tid = threadIdx.x;
    const int row = blockIdx.x;
    float4* rowp = reinterpret_cast<float4*>(S + (size_t)row * NN);

    // load row + local max
    float lmax = -3.0e38f;
    for (int i = tid; i < NN / 4; i += 512) {
        float4 v = rowp[i];
        sbuf[i] = v;
        lmax = fmaxf(lmax, fmaxf(fmaxf(v.x, v.y), fmaxf(v.z, v.w)));
    }
    #pragma unroll
    for (int o = 16; o; o >>= 1)
        lmax = fmaxf(lmax, __shfl_xor_sync(0xFFFFFFFFu, lmax, o));
    if ((tid & 31) == 0) sred[tid >> 5] = lmax;
    __syncthreads();
    float m = sred[0];
    #pragma unroll
    for (int w = 1; w < 16; w++) m = fmaxf(m, sred[w]);
    __syncthreads();

    // sum of exp(s - m)
    float lsum = 0.0f;
    for (int i = tid; i < NN / 4; i += 512) {
        float4 v = sbuf[i];
        lsum += __expf(v.x - m) + __expf(v.y - m) +
                __expf(v.z - m) + __expf(v.w - m);
    }
    #pragma unroll
    for (int o = 16; o; o >>= 1)
        lsum += __shfl_xor_sync(0xFFFFFFFFu, lsum, o);
    if ((tid & 31) == 0) sred[tid >> 5] = lsum;
    __syncthreads();
    float Z = 0.0f;
    #pragma unroll
    for (int w = 0; w < 16; w++) Z += sred[w];

    const float invZ = 1.0f / Z;
    const float avg  = 1.0f / (float)NN;

    for (int i = tid; i < NN / 4; i += 512) {
        float4 v = sbuf[i];
        float px = __expf(v.x - m) * invZ;
        float py = __expf(v.y - m) * invZ;
        float pz = __expf(v.z - m) * invZ;
        float pw = __expf(v.w - m) * invZ;
        float4 o;
        o.x = (px < avg) ? 0.0f : px;
        o.y = (py < avg) ? 0.0f : py;
        o.z = (pz < avg) ? 0.0f : pz;
        o.w = (pw < avg) ? 0.0f : pw;
        rowp[i] = o;
    }
}

// ---------------------------------------------------------------------------
extern "C" void kernel_launch(void* const* d_in, const int* in_sizes, int n_in,
                              void* d_out, int out_size) {
    const float* X = (const float*)d_in[0];
    float* Ad = (float*)d_out;                       // first N*N floats
    float* As = (float*)d_out + (size_t)NN * NN;     // second N*N floats

    k0_tables<<<1, 128>>>();
    k1_gemm<<<dim3(NN / 128, NN / 64), 256>>>(X, As, Ad);  // 50 x 100 CTAs
    k2_softmax<<<NN, 512>>>(As);
}

// round 4
// speedup vs baseline: 1.8282x; 1.8282x over previous
#include <cuda_runtime.h>
#include <cuda_bf16.h>
#include <cstdint>

#define NN 6400
#define CC 64
#define CP 128          // augmented K: [hi | lo] bf16
#define HH 80

// augmented bf16 operand matrix P = [bf16(x) | bf16(x - bf16(x))], row-major 6400x128
__device__ __nv_bfloat16 g_P[(size_t)NN * CP];

// ---------------------------------------------------------------------------
// kprep: build P. One thread = 8 consecutive floats of one row.
// ---------------------------------------------------------------------------
__global__ __launch_bounds__(256) void kprep(const float* __restrict__ X) {
    int t = blockIdx.x * 256 + threadIdx.x;      // 51200 threads
    int row = t >> 3;
    int seg = (t & 7) * 8;
    const float* src = X + (size_t)row * CC + seg;
    __nv_bfloat16* hi = g_P + (size_t)row * CP + seg;
    __nv_bfloat16* lo = hi + CC;
    #pragma unroll
    for (int i = 0; i < 8; i++) {
        float x = src[i];
        __nv_bfloat16 h = __float2bfloat16_rn(x);
        float r = x - __bfloat162float(h);
        hi[i] = h;
        lo[i] = __float2bfloat16_rn(r);
    }
}

// ---------------------------------------------------------------------------
// k1: S = P @ P^T via mma.sync m16n8k16 bf16 (fp32 accum). Raw logits -> As.
// CTA tile 128x128, 256 threads; warp grid 4(M) x 2(N), warp tile 32x64.
// smem tiles padded to stride 72 bf16 (144B) for conflict-free fragment LDS.
// ---------------------------------------------------------------------------
#define SSTR 72

__device__ __forceinline__ void mma16816(float* c, const uint32_t* a,
                                         const uint32_t* b) {
    asm volatile(
        "mma.sync.aligned.m16n8k16.row.col.f32.bf16.bf16.f32 "
        "{%0,%1,%2,%3}, {%4,%5,%6,%7}, {%8,%9}, {%0,%1,%2,%3};"
        : "+f"(c[0]), "+f"(c[1]), "+f"(c[2]), "+f"(c[3])
        : "r"(a[0]), "r"(a[1]), "r"(a[2]), "r"(a[3]),
          "r"(b[0]), "r"(b[1]));
}

__global__ __launch_bounds__(256, 2) void k1_gemm(float* __restrict__ S) {
    __shared__ __nv_bfloat16 sA[128 * SSTR];   // 18 KB
    __shared__ __nv_bfloat16 sB[128 * SSTR];   // 18 KB

    const int tid  = threadIdx.x;
    const int lane = tid & 31;
    const int wid  = tid >> 5;
    const int warpM = wid & 3;     // 4 row groups of 32
    const int warpN = wid >> 2;    // 2 col groups of 64
    const int r0 = blockIdx.y * 128;
    const int c0 = blockIdx.x * 128;

    const int g   = lane >> 2;     // groupID 0..7
    const int tg  = lane & 3;      // thread-in-group

    float acc[2][8][4];
    #pragma unroll
    for (int mt = 0; mt < 2; mt++)
        #pragma unroll
        for (int nt = 0; nt < 8; nt++)
            #pragma unroll
            for (int i = 0; i < 4; i++)
                acc[mt][nt][i] = 0.0f;

    const int ldrow = tid >> 1;          // 0..127
    const int ldhalf = (tid & 1) * 32;   // which 32-k half

    #pragma unroll
    for (int kc = 0; kc < 2; kc++) {
        if (kc) __syncthreads();
        // stage A rows [r0..r0+127], k in [kc*64, kc*64+64)
        {
            const uint4* src = reinterpret_cast<const uint4*>(
                g_P + (size_t)(r0 + ldrow) * CP + kc * 64 + ldhalf);
            uint4* dst = reinterpret_cast<uint4*>(&sA[ldrow * SSTR + ldhalf]);
            dst[0] = src[0]; dst[1] = src[1]; dst[2] = src[2]; dst[3] = src[3];
        }
        {
            const uint4* src = reinterpret_cast<const uint4*>(
                g_P + (size_t)(c0 + ldrow) * CP + kc * 64 + ldhalf);
            uint4* dst = reinterpret_cast<uint4*>(&sB[ldrow * SSTR + ldhalf]);
            dst[0] = src[0]; dst[1] = src[1]; dst[2] = src[2]; dst[3] = src[3];
        }
        __syncthreads();

        #pragma unroll
        for (int t = 0; t < 4; t++) {
            const int kb = t * 16;
            uint32_t afr[2][4];
            #pragma unroll
            for (int mt = 0; mt < 2; mt++) {
                int r = warpM * 32 + mt * 16 + g;
                afr[mt][0] = *reinterpret_cast<const uint32_t*>(&sA[r * SSTR + kb + tg * 2]);
                afr[mt][1] = *reinterpret_cast<const uint32_t*>(&sA[(r + 8) * SSTR + kb + tg * 2]);
                afr[mt][2] = *reinterpret_cast<const uint32_t*>(&sA[r * SSTR + kb + 8 + tg * 2]);
                afr[mt][3] = *reinterpret_cast<const uint32_t*>(&sA[(r + 8) * SSTR + kb + 8 + tg * 2]);
            }
            uint32_t bfr[8][2];
            #pragma unroll
            for (int nt = 0; nt < 8; nt++) {
                int n = warpN * 64 + nt * 8 + g;
                bfr[nt][0] = *reinterpret_cast<const uint32_t*>(&sB[n * SSTR + kb + tg * 2]);
                bfr[nt][1] = *reinterpret_cast<const uint32_t*>(&sB[n * SSTR + kb + 8 + tg * 2]);
            }
            #pragma unroll
            for (int mt = 0; mt < 2; mt++)
                #pragma unroll
                for (int nt = 0; nt < 8; nt++)
                    mma16816(acc[mt][nt], afr[mt], bfr[nt]);
        }
    }

    // epilogue: per mma tile, lane writes 2 float2 rows
    #pragma unroll
    for (int mt = 0; mt < 2; mt++) {
        #pragma unroll
        for (int nt = 0; nt < 8; nt++) {
            int row = r0 + warpM * 32 + mt * 16 + g;
            int col = c0 + warpN * 64 + nt * 8 + tg * 2;
            float2 v0 = make_float2(acc[mt][nt][0], acc[mt][nt][1]);
            float2 v1 = make_float2(acc[mt][nt][2], acc[mt][nt][3]);
            *reinterpret_cast<float2*>(&S[(size_t)row * NN + col]) = v0;
            *reinterpret_cast<float2*>(&S[(size_t)(row + 8) * NN + col]) = v1;
        }
    }
}

// ---------------------------------------------------------------------------
// k3: analytic Ad. Tables built per block (amortized by grid-stride x10).
// Ad[i][j] = E[|ri-rj|]*E[|ci-cj|] / (S1[ri]*S1[ci]-1), diag = 0.
// ---------------------------------------------------------------------------
#define ADBLK 4000
#define ADIT 10

__global__ __launch_bounds__(256) void k3_ad(float* __restrict__ Ad) {
    __shared__ float sE[HH];
    __shared__ float sS1[HH];
    int tid = threadIdx.x;
    if (tid < HH) sE[tid] = __expf(-0.5f * (float)(tid * tid));
    __syncthreads();
    if (tid < HH) {
        float s = 0.0f;
        #pragma unroll 8
        for (int r = 0; r < HH; r++) {
            int d = tid - r; d = d < 0 ? -d : d;
            s += sE[d];
        }
        sS1[tid] = s;
    }
    __syncthreads();

    #pragma unroll
    for (int it = 0; it < ADIT; it++) {
        size_t q = (size_t)blockIdx.x * (256 * ADIT) + it * 256 + tid;
        size_t e = q * 4;
        int i  = (int)(e / NN);
        int j0 = (int)(e - (size_t)i * NN);
        int ri = i / HH,  ci = i - ri * HH;
        int rj = j0 / HH, cj = j0 - rj * HH;

        int dr = ri - rj; dr = dr < 0 ? -dr : dr;
        float inv  = 1.0f / (sS1[ri] * sS1[ci] - 1.0f);
        float base = sE[dr] * inv;

        int d0 = ci - cj;       d0 = d0 < 0 ? -d0 : d0;
        int d1 = ci - (cj + 1); d1 = d1 < 0 ? -d1 : d1;
        int d2 = ci - (cj + 2); d2 = d2 < 0 ? -d2 : d2;
        int d3 = ci - (cj + 3); d3 = d3 < 0 ? -d3 : d3;
        float4 o;
        o.x = base * sE[d0];
        o.y = base * sE[d1];
        o.z = base * sE[d2];
        o.w = base * sE[d3];
        if (i == j0    ) o.x = 0.0f;
        if (i == j0 + 1) o.y = 0.0f;
        if (i == j0 + 2) o.z = 0.0f;
        if (i == j0 + 3) o.w = 0.0f;
        reinterpret_cast<float4*>(Ad)[q] = o;
    }
}

// ---------------------------------------------------------------------------
// k2: per-row softmax finalize (in place). One row per CTA, 512 threads.
// mean(softmax_row) == 1/N exactly -> threshold e < Z/N on exp values.
// ---------------------------------------------------------------------------
__global__ __launch_bounds__(512) void k2_softmax(float* __restrict__ S) {
    __shared__ float4 sbuf[NN / 4];   // 25.6 KB row cache
    __shared__ float  sred[16];

    const int tid = threadIdx.x;
    const int row = blockIdx.x;
    float4* rowp = reinterpret_cast<float4*>(S + (size_t)row * NN);

    // pass 1: load row + max
    float lmax = -3.0e38f;
    for (int i = tid; i < NN / 4; i += 512) {
        float4 v = rowp[i];
        sbuf[i] = v;
        lmax = fmaxf(lmax, fmaxf(fmaxf(v.x, v.y), fmaxf(v.z, v.w)));
    }
    #pragma unroll
    for (int o = 16; o; o >>= 1)
        lmax = fmaxf(lmax, __shfl_xor_sync(0xFFFFFFFFu, lmax, o));
    if ((tid & 31) == 0) sred[tid >> 5] = lmax;
    __syncthreads();
    float m = sred[0];
    #pragma unroll
    for (int w = 1; w < 16; w++) m = fmaxf(m, sred[w]);
    __syncthreads();

    // pass 2: e = exp(v-m) stored back to sbuf, accumulate sum
    float lsum = 0.0f;
    for (int i = tid; i < NN / 4; i += 512) {
        float4 v = sbuf[i];
        v.x = __expf(v.x - m);
        v.y = __expf(v.y - m);
        v.z = __expf(v.z - m);
        v.w = __expf(v.w - m);
        sbuf[i] = v;
        lsum += v.x + v.y + v.z + v.w;
    }
    #pragma unroll
    for (int o = 16; o; o >>= 1)
        lsum += __shfl_xor_sync(0xFFFFFFFFu, lsum, o);
    if ((tid & 31) == 0) sred[tid >> 5] = lsum;
    __syncthreads();
    float Z = 0.0f;
    #pragma unroll
    for (int w = 0; w < 16; w++) Z += sred[w];

    const float invZ = 1.0f / Z;
    const float thr  = Z * (1.0f / (float)NN);

    // pass 3: scale + threshold + store
    for (int i = tid; i < NN / 4; i += 512) {
        float4 e = sbuf[i];
        float4 o;
        o.x = (e.x < thr) ? 0.0f : e.x * invZ;
        o.y = (e.y < thr) ? 0.0f : e.y * invZ;
        o.z = (e.z < thr) ? 0.0f : e.z * invZ;
        o.w = (e.w < thr) ? 0.0f : e.w * invZ;
        rowp[i] = o;
    }
}

// ---------------------------------------------------------------------------
extern "C" void kernel_launch(void* const* d_in, const int* in_sizes, int n_in,
                              void* d_out, int out_size) {
    const float* X = (const float*)d_in[0];
    float* Ad = (float*)d_out;                       // first N*N floats
    float* As = (float*)d_out + (size_t)NN * NN;     // second N*N floats

    kprep<<<200, 256>>>(X);
    k3_ad<<<ADBLK, 256>>>(Ad);
    k1_gemm<<<dim3(NN / 128, NN / 128), 256>>>(As);  // 50 x 50 CTAs
    k2_softmax<<<NN, 512>>>(As);
}